// round 5
// baseline (speedup 1.0000x reference)
#include <cuda_runtime.h>
#include <cuda_bf16.h>
#include <math_constants.h>

// AttentionMax: correlation[b,s] = <q[b], sub[b,s]>, argmax over s, one-hot out [bz, ns, 1]
// bz=4096, ns=256, d=128, fp32. Memory-bound: 512MB stream of feat_sub.
//
// R5: back to non-persistent grid (R4 persistent regressed: barrier-serialized
// batch boundaries). Occupancy 4->6 CTAs/SM: 2-row double-buffered pipeline
// (16 buffer regs) + reduce2, __launch_bounds__(256,6) to fit 48 warps/SM.

#define NS 256
#define D  128

// Fold 2 rows' per-lane partials into full row sums.
// Result: lane L holds sum of row base + ((L>>4)&1), replicated across 16 lanes.
__device__ __forceinline__ float reduce2(float p0, float p1, int lane)
{
    const unsigned FULL = 0xffffffffu;
    bool hi16 = (lane & 16) != 0;
    float s = hi16 ? p0 : p1;                 // value given away
    float r = __shfl_xor_sync(FULL, s, 16);
    float acc = (hi16 ? p1 : p0) + r;
    acc += __shfl_xor_sync(FULL, acc, 8);
    acc += __shfl_xor_sync(FULL, acc, 4);
    acc += __shfl_xor_sync(FULL, acc, 2);
    acc += __shfl_xor_sync(FULL, acc, 1);
    return acc;
}

__device__ __forceinline__ float dot4(float4 v, float4 q)
{
    float p = v.x * q.x;
    p = fmaf(v.y, q.y, p);
    p = fmaf(v.z, q.z, p);
    p = fmaf(v.w, q.w, p);
    return p;
}

__global__ __launch_bounds__(256, 6)
void attention_max_kernel(const float* __restrict__ q,
                          const float* __restrict__ sub,
                          float* __restrict__ out)
{
    const int b    = blockIdx.x;
    const int tid  = threadIdx.x;
    const int warp = tid >> 5;        // 0..7, each warp owns 32 support rows
    const int lane = tid & 31;
    const int myrow = (lane >> 4) & 1;
    const unsigned FULL = 0xffffffffu;

    const float4 qc = reinterpret_cast<const float4*>(q + (size_t)b * D)[lane];

    const float4* base = reinterpret_cast<const float4*>(
        sub + ((size_t)b * NS + warp * 32) * D);

    float bestv = -CUDART_INF_F;
    int   besti = 0;

    float4 va0 = __ldcs(&base[0 * 32 + lane]);
    float4 va1 = __ldcs(&base[1 * 32 + lane]);

#pragma unroll
    for (int rr = 0; rr < 32; rr += 4) {
        // prefetch rows rr+2, rr+3 while reducing rr, rr+1
        float4 vb0 = __ldcs(&base[(rr + 2) * 32 + lane]);
        float4 vb1 = __ldcs(&base[(rr + 3) * 32 + lane]);

        {
            float s = reduce2(dot4(va0, qc), dot4(va1, qc), lane);
            if (s > bestv) { bestv = s; besti = warp * 32 + rr + myrow; }
        }

        if (rr + 4 < 32) {
            va0 = __ldcs(&base[(rr + 4) * 32 + lane]);
            va1 = __ldcs(&base[(rr + 5) * 32 + lane]);
        }

        {
            float s = reduce2(dot4(vb0, qc), dot4(vb1, qc), lane);
            if (s > bestv) { bestv = s; besti = warp * 32 + rr + 2 + myrow; }
        }
    }

    // Cross-lane argmax (value max, smaller index wins ties).
#pragma unroll
    for (int m = 16; m > 0; m >>= 1) {
        float ov = __shfl_xor_sync(FULL, bestv, m);
        int   oi = __shfl_xor_sync(FULL, besti, m);
        if (ov > bestv || (ov == bestv && oi < besti)) { bestv = ov; besti = oi; }
    }

    __shared__ float wval[8];
    __shared__ int   widx[8];

    if (lane == 0) { wval[warp] = bestv; widx[warp] = besti; }
    __syncthreads();

    // Every thread redundantly reduces the 8 warp results (no second barrier).
    float bv = wval[0];
    int   bi = widx[0];
#pragma unroll
    for (int w = 1; w < 8; ++w)
        if (wval[w] > bv) { bv = wval[w]; bi = widx[w]; }

    out[(size_t)b * NS + tid] = (tid == bi) ? 1.0f : 0.0f;
}

extern "C" void kernel_launch(void* const* d_in, const int* in_sizes, int n_in,
                              void* d_out, int out_size)
{
    const float* q   = (const float*)d_in[0];   // [4096, 128]
    const float* sub = (const float*)d_in[1];   // [4096, 256, 128]
    float*       out = (float*)d_out;           // [4096, 256, 1]

    const int bz = in_sizes[0] / D;             // 4096

    attention_max_kernel<<<bz, NS>>>(q, sub, out);
}